// round 10
// baseline (speedup 1.0000x reference)
#include <cuda_runtime.h>
#include <math.h>
#include <stdint.h>

#define NB 4
#define SEQ 2048
#define DMODEL 1024
#define NH 16
#define HD 64
#define NTOK (NB*SEQ)      /* 8192 */
#define DFF 4096

// ---------------- scratch (device globals; no allocations allowed) ----------
__device__ float g_ln [(size_t)NTOK*DMODEL];
__device__ float g_q  [(size_t)NTOK*DMODEL];
__device__ float g_k  [(size_t)NTOK*DMODEL];
__device__ float g_v  [(size_t)NTOK*DMODEL];
__device__ float g_ctx[(size_t)NTOK*DMODEL];
__device__ float g_x1 [(size_t)NTOK*DMODEL];
__device__ float g_h2 [(size_t)NTOK*DFF];
// tf32-pre-rounded weight copies (same layout as the originals)
__device__ float g_wqkvR[(size_t)DMODEL*3*DMODEL];
__device__ float g_woutR[(size_t)DMODEL*DMODEL];
__device__ float g_w1R  [(size_t)DMODEL*DFF];
__device__ float g_w2R  [(size_t)DFF*DMODEL];

// ---------------- helpers ----------------------------------------------------
__device__ __forceinline__ float tf32r(float x){
    unsigned u; asm("cvt.rna.tf32.f32 %0, %1;" : "=r"(u) : "f"(x));
    return __uint_as_float(u);
}
__device__ __forceinline__ float gelu_fast(float x){
    float u = 0.7978845608028654f*(x + 0.044715f*x*x*x);
    float th; asm("tanh.approx.f32 %0, %1;" : "=f"(th) : "f"(u));
    return 0.5f*x*(1.0f + th);
}
__device__ __forceinline__ void mma8(float* c, const unsigned* a, const unsigned* b){
    asm volatile(
        "mma.sync.aligned.m16n8k8.row.col.f32.tf32.tf32.f32 "
        "{%0,%1,%2,%3}, {%4,%5,%6,%7}, {%8,%9}, {%0,%1,%2,%3};\n"
        : "+f"(c[0]), "+f"(c[1]), "+f"(c[2]), "+f"(c[3])
        : "r"(a[0]), "r"(a[1]), "r"(a[2]), "r"(a[3]), "r"(b[0]), "r"(b[1]));
}
__device__ __forceinline__ void cpa16(void* smem_dst, const void* gsrc){
    unsigned d = (unsigned)__cvta_generic_to_shared(smem_dst);
    asm volatile("cp.async.cg.shared.global [%0], [%1], 16;\n" :: "r"(d), "l"(gsrc));
}
#define CP_COMMIT() asm volatile("cp.async.commit_group;\n" ::: "memory")
#define CP_WAIT1()  asm volatile("cp.async.wait_group 1;\n" ::: "memory")

// ---------------- weight tf32 pre-round --------------------------------------
__global__ __launch_bounds__(256) void round_tf32_kernel(
    const float* __restrict__ src, float* __restrict__ dst)
{
    size_t i = ((size_t)blockIdx.x*256 + threadIdx.x)*4;
    float4 v = *(const float4*)(src + i);
    v.x = tf32r(v.x); v.y = tf32r(v.y); v.z = tf32r(v.z); v.w = tf32r(v.w);
    *(float4*)(dst + i) = v;
}

// ---------------- LayerNorm (tf32-rounded output) ----------------------------
__global__ __launch_bounds__(256) void ln_kernel(const float* __restrict__ x,
        const float* __restrict__ g, const float* __restrict__ s,
        float* __restrict__ out)
{
    int row = blockIdx.x;
    int t = threadIdx.x;
    const float4* xr = (const float4*)(x + (size_t)row*DMODEL);
    float4 v = xr[t];
    float sum = v.x+v.y+v.z+v.w;
    float sq  = v.x*v.x+v.y*v.y+v.z*v.z+v.w*v.w;
    #pragma unroll
    for (int o=16;o>0;o>>=1){
        sum += __shfl_xor_sync(0xffffffffu, sum, o);
        sq  += __shfl_xor_sync(0xffffffffu, sq , o);
    }
    __shared__ float red[16];
    if ((t&31)==0){ red[t>>5] = sum; red[8+(t>>5)] = sq; }
    __syncthreads();
    sum = 0.0f; sq = 0.0f;
    #pragma unroll
    for (int w=0; w<8; w++){ sum += red[w]; sq += red[8+w]; }
    float mean = sum * (1.0f/DMODEL);
    float var  = sq  * (1.0f/DMODEL) - mean*mean;
    float rinv = rsqrtf(var + 1e-5f);
    float4 gv = ((const float4*)g)[t];
    float4 sv = ((const float4*)s)[t];
    float4 o;
    o.x = tf32r((v.x-mean)*rinv*gv.x + sv.x);
    o.y = tf32r((v.y-mean)*rinv*gv.y + sv.y);
    o.z = tf32r((v.z-mean)*rinv*gv.z + sv.z);
    o.w = tf32r((v.w-mean)*rinv*gv.w + sv.w);
    ((float4*)(out + (size_t)row*DMODEL))[t] = o;
}

// ---------------- TF32 tensor-core GEMM (3-stage cp.async pipeline) ----------
// 128x128 CTA tile, K-slab 32, 8 warps (2x4), warp tile 64x32 as 4x4 m16n8k8.
// Inputs must already be tf32-rounded (weights pre-rounded; activations
// rounded at their producers) so in-mma RZ truncation is lossless.
// EPI: 0 plain, 1 +bias+residual, 2 +bias+gelu(->tf32), 3 qkv scatter.
struct GSmem {
    float As[3][128][36];
    float Bs[3][32][136];
};
extern __shared__ char gsm_raw[];

template<int EPI>
__global__ __launch_bounds__(256,2) void tfgemm_kernel(
    const float* __restrict__ A, const float* __restrict__ B,
    const float* __restrict__ bias, const float* __restrict__ res,
    float* __restrict__ C,
    float* __restrict__ Oq, float* __restrict__ Ok, float* __restrict__ Ov,
    int M, int N, int K)
{
    GSmem* sm = (GSmem*)gsm_raw;
    int t = threadIdx.x;
    int lane = t & 31, w = t >> 5;
    int wm = w >> 2, wn = w & 3;        // warp grid 2 x 4
    int g = lane >> 2, tig = lane & 3;  // mma groupID / thread-in-group
    int m0 = blockIdx.y * 128, n0 = blockIdx.x * 128;

    const int arow = t >> 1, acol = (t & 1) * 4;   // A: 128 rows x 32 cols
    const int brow = t >> 3, bcol = (t & 7) * 4;   // B: 32 rows x 128 cols
    const float* Abase = A + (size_t)(m0 + arow)*K + acol;
    const float* Bbase = B + (size_t)brow*N + n0 + bcol;

    float acc[4][4][4];
    #pragma unroll
    for (int i=0;i<4;i++)
    #pragma unroll
    for (int j=0;j<4;j++)
    #pragma unroll
    for (int r=0;r<4;r++) acc[i][j][r] = 0.0f;

    // issue one K-slab's async copies into stage slab%3
    auto issue = [&](int slab){
        int buf = slab % 3;
        const float* Ap = Abase + slab*32;
        #pragma unroll
        for (int i=0;i<4;i++)
            cpa16(&sm->As[buf][arow][acol + 8*i], Ap + 8*i);
        const float* Bp = Bbase + (size_t)slab*32*N;
        #pragma unroll
        for (int i=0;i<4;i++)
            cpa16(&sm->Bs[buf][brow][bcol + 32*i], Bp + 32*i);
    };

    issue(0); CP_COMMIT();
    issue(1); CP_COMMIT();

    int nslab = K >> 5;
    for (int s=0; s<nslab; s++){
        int buf = s % 3;
        CP_WAIT1();                 // slab s landed (one newer may be in flight)
        __syncthreads();            // visibility + all warps done with buf (s-1)%3
        if (s + 2 < nslab) issue(s + 2);
        CP_COMMIT();                // exactly one group per iteration (may be empty)
        #pragma unroll
        for (int ks=0; ks<4; ks++){
            int kk = ks*8;
            unsigned af[4][4], bf[4][2];
            #pragma unroll
            for (int mt=0; mt<4; mt++){
                int m = wm*64 + mt*16;
                af[mt][0] = __float_as_uint(sm->As[buf][m+g  ][kk+tig  ]);
                af[mt][1] = __float_as_uint(sm->As[buf][m+g+8][kk+tig  ]);
                af[mt][2] = __float_as_uint(sm->As[buf][m+g  ][kk+tig+4]);
                af[mt][3] = __float_as_uint(sm->As[buf][m+g+8][kk+tig+4]);
            }
            #pragma unroll
            for (int nt=0; nt<4; nt++){
                int n = wn*32 + nt*8;
                bf[nt][0] = __float_as_uint(sm->Bs[buf][kk+tig  ][n+g]);
                bf[nt][1] = __float_as_uint(sm->Bs[buf][kk+tig+4][n+g]);
            }
            #pragma unroll
            for (int mt=0; mt<4; mt++)
            #pragma unroll
            for (int nt=0; nt<4; nt++)
                mma8(acc[mt][nt], af[mt], bf[nt]);
        }
    }

    // ---------------- epilogue (float2 per half-fragment) --------------
    #pragma unroll
    for (int mt=0; mt<4; mt++){
        #pragma unroll
        for (int nt=0; nt<4; nt++){
            int col = n0 + wn*32 + nt*8 + 2*tig;
            #pragma unroll
            for (int hh=0; hh<2; hh++){
                int row = m0 + wm*64 + mt*16 + g + hh*8;
                float2 v = make_float2(acc[mt][nt][hh*2+0], acc[mt][nt][hh*2+1]);
                if (EPI == 0){
                    *(float2*)(C + (size_t)row*N + col) = v;
                } else if (EPI == 1){
                    float2 bb = *(const float2*)(bias + col);
                    float2 rr = *(const float2*)(res + (size_t)row*N + col);
                    v.x += bb.x + rr.x; v.y += bb.y + rr.y;
                    *(float2*)(C + (size_t)row*N + col) = v;
                } else if (EPI == 2){
                    float2 bb = *(const float2*)(bias + col);
                    v.x = tf32r(gelu_fast(v.x + bb.x));
                    v.y = tf32r(gelu_fast(v.y + bb.y));
                    *(float2*)(C + (size_t)row*N + col) = v;
                } else {
                    int which = col >> 10;
                    int h = (col >> 6) & (NH-1);
                    int d = col & (HD-1);
                    int b = row >> 11;
                    int sg = row & (SEQ-1);
                    float* o = (which==0) ? Oq : ((which==1) ? Ok : Ov);
                    *(float2*)(o + ((size_t)((b*NH + h)*SEQ + sg))*HD + d) = v;
                }
            }
        }
    }
}

// ---------------- Flash attention (TF32 mma, causal) ------------------------
// 64-query tile, 64-key steps, 128 threads / 4 warps; warp w owns query rows
// [w*16, w*16+16): softmax row stats warp-local, P warp-private.
struct FlashSmemT {
    float Qs[64][68];
    float Ks[64][68];
    float Vs[64][72];
    float Ps[64][68];
};
extern __shared__ char flash_dyn[];

__global__ __launch_bounds__(128) void flash_tc_kernel(
    const float* __restrict__ Q, const float* __restrict__ K,
    const float* __restrict__ V, float* __restrict__ ctx)
{
    FlashSmemT* sm = (FlashSmemT*)flash_dyn;
    int t = threadIdx.x;
    int lane = t & 31, w = t >> 5;
    int g = lane >> 2, tig = lane & 3;
    int qb = blockIdx.x, bh = blockIdx.y;
    int mw = w * 16;

    const float* Qb = Q + ((size_t)bh*SEQ + (size_t)qb*64)*HD;
    const float* Kb = K + (size_t)bh*SEQ*HD;
    const float* Vb = V + (size_t)bh*SEQ*HD;

    #pragma unroll
    for (int i=0;i<8;i++){
        int cidx = t + 128*i;
        int r = cidx >> 4, c = (cidx & 15) * 4;
        float4 v = *(const float4*)(Qb + r*HD + c);
        sm->Qs[r][c+0] = tf32r(v.x*0.125f);
        sm->Qs[r][c+1] = tf32r(v.y*0.125f);
        sm->Qs[r][c+2] = tf32r(v.z*0.125f);
        sm->Qs[r][c+3] = tf32r(v.w*0.125f);
    }

    float m0 = -1e30f, m1 = -1e30f, l0 = 0.0f, l1 = 0.0f;
    float acc_o[8][4];
    #pragma unroll
    for (int nt=0; nt<8; nt++)
    #pragma unroll
    for (int r=0; r<4; r++) acc_o[nt][r] = 0.0f;

    for (int jt=0; jt<=qb; jt++){
        __syncthreads();
        const float* Kp = Kb + (size_t)jt*64*HD;
        const float* Vp = Vb + (size_t)jt*64*HD;
        #pragma unroll
        for (int i=0;i<8;i++){
            int cidx = t + 128*i;
            int r = cidx >> 4, c = (cidx & 15) * 4;
            float4 kv = *(const float4*)(Kp + r*HD + c);
            sm->Ks[r][c+0] = tf32r(kv.x); sm->Ks[r][c+1] = tf32r(kv.y);
            sm->Ks[r][c+2] = tf32r(kv.z); sm->Ks[r][c+3] = tf32r(kv.w);
            float4 vv = *(const float4*)(Vp + r*HD + c);
            sm->Vs[r][c+0] = tf32r(vv.x); sm->Vs[r][c+1] = tf32r(vv.y);
            sm->Vs[r][c+2] = tf32r(vv.z); sm->Vs[r][c+3] = tf32r(vv.w);
        }
        __syncthreads();

        float acc_s[8][4];
        #pragma unroll
        for (int nt=0; nt<8; nt++)
        #pragma unroll
        for (int r=0; r<4; r++) acc_s[nt][r] = 0.0f;
        #pragma unroll
        for (int ks=0; ks<8; ks++){
            int kk = ks*8;
            unsigned af[4];
            af[0] = __float_as_uint(sm->Qs[mw+g  ][kk+tig  ]);
            af[1] = __float_as_uint(sm->Qs[mw+g+8][kk+tig  ]);
            af[2] = __float_as_uint(sm->Qs[mw+g  ][kk+tig+4]);
            af[3] = __float_as_uint(sm->Qs[mw+g+8][kk+tig+4]);
            #pragma unroll
            for (int nt=0; nt<8; nt++){
                unsigned bf[2];
                bf[0] = __float_as_uint(sm->Ks[nt*8+g][kk+tig  ]);
                bf[1] = __float_as_uint(sm->Ks[nt*8+g][kk+tig+4]);
                mma8(acc_s[nt], af, bf);
            }
        }

        if (jt == qb){
            int i0 = mw + g;
            #pragma unroll
            for (int nt=0; nt<8; nt++){
                int j = nt*8 + 2*tig;
                if (j   > i0)   acc_s[nt][0] = -1e30f;
                if (j+1 > i0)   acc_s[nt][1] = -1e30f;
                if (j   > i0+8) acc_s[nt][2] = -1e30f;
                if (j+1 > i0+8) acc_s[nt][3] = -1e30f;
            }
        }

        float mx0 = -1e30f, mx1 = -1e30f;
        #pragma unroll
        for (int nt=0; nt<8; nt++){
            mx0 = fmaxf(mx0, fmaxf(acc_s[nt][0], acc_s[nt][1]));
            mx1 = fmaxf(mx1, fmaxf(acc_s[nt][2], acc_s[nt][3]));
        }
        mx0 = fmaxf(mx0, __shfl_xor_sync(0xffffffffu, mx0, 1));
        mx0 = fmaxf(mx0, __shfl_xor_sync(0xffffffffu, mx0, 2));
        mx1 = fmaxf(mx1, __shfl_xor_sync(0xffffffffu, mx1, 1));
        mx1 = fmaxf(mx1, __shfl_xor_sync(0xffffffffu, mx1, 2));
        float mn0 = fmaxf(m0, mx0), mn1 = fmaxf(m1, mx1);
        float al0 = __expf(m0 - mn0), al1 = __expf(m1 - mn1);
        float s0 = 0.0f, s1 = 0.0f;
        #pragma unroll
        for (int nt=0; nt<8; nt++){
            float p00 = __expf(acc_s[nt][0] - mn0);
            float p01 = __expf(acc_s[nt][1] - mn0);
            float p10 = __expf(acc_s[nt][2] - mn1);
            float p11 = __expf(acc_s[nt][3] - mn1);
            s0 += p00 + p01; s1 += p10 + p11;
            *(float2*)&sm->Ps[mw+g  ][nt*8 + 2*tig] = make_float2(tf32r(p00), tf32r(p01));
            *(float2*)&sm->Ps[mw+g+8][nt*8 + 2*tig] = make_float2(tf32r(p10), tf32r(p11));
        }
        s0 += __shfl_xor_sync(0xffffffffu, s0, 1);
        s0 += __shfl_xor_sync(0xffffffffu, s0, 2);
        s1 += __shfl_xor_sync(0xffffffffu, s1, 1);
        s1 += __shfl_xor_sync(0xffffffffu, s1, 2);
        m0 = mn0; m1 = mn1;
        l0 = l0*al0 + s0; l1 = l1*al1 + s1;
        #pragma unroll
        for (int nt=0; nt<8; nt++){
            acc_o[nt][0] *= al0; acc_o[nt][1] *= al0;
            acc_o[nt][2] *= al1; acc_o[nt][3] *= al1;
        }

        __syncwarp();

        #pragma unroll
        for (int ks=0; ks<8; ks++){
            int kk = ks*8;
            unsigned af[4];
            af[0] = __float_as_uint(sm->Ps[mw+g  ][kk+tig  ]);
            af[1] = __float_as_uint(sm->Ps[mw+g+8][kk+tig  ]);
            af[2] = __float_as_uint(sm->Ps[mw+g  ][kk+tig+4]);
            af[3] = __float_as_uint(sm->Ps[mw+g+8][kk+tig+4]);
            #pragma unroll
            for (int nt=0; nt<8; nt++){
                unsigned bf[2];
                bf[0] = __float_as_uint(sm->Vs[kk+tig  ][nt*8+g]);
                bf[1] = __float_as_uint(sm->Vs[kk+tig+4][nt*8+g]);
                mma8(acc_o[nt], af, bf);
            }
        }
    }

    // normalize, tf32-round (feeds Wout GEMM), write ctx in [B,S,D]
    float inv0 = 1.0f/l0, inv1 = 1.0f/l1;
    int b = bh >> 4, h = bh & (NH-1);
    int r0 = qb*64 + mw + g, r1 = r0 + 8;
    #pragma unroll
    for (int nt=0; nt<8; nt++){
        int col = h*HD + nt*8 + 2*tig;
        *(float2*)(ctx + (size_t)(b*SEQ + r0)*DMODEL + col) =
            make_float2(tf32r(acc_o[nt][0]*inv0), tf32r(acc_o[nt][1]*inv0));
        *(float2*)(ctx + (size_t)(b*SEQ + r1)*DMODEL + col) =
            make_float2(tf32r(acc_o[nt][2]*inv1), tf32r(acc_o[nt][3]*inv1));
    }
}

// ---------------- launch ----------------------------------------------------
extern "C" void kernel_launch(void* const* d_in, const int* in_sizes, int n_in,
                              void* d_out, int out_size)
{
    (void)in_sizes; (void)n_in; (void)out_size;
    const float* x    = (const float*)d_in[0];
    const float* Wqkv = (const float*)d_in[1];
    const float* Wout = (const float*)d_in[2];
    const float* bout = (const float*)d_in[3];
    const float* W1   = (const float*)d_in[4];
    const float* b1   = (const float*)d_in[5];
    const float* W2   = (const float*)d_in[6];
    const float* b2   = (const float*)d_in[7];
    const float* g1   = (const float*)d_in[8];
    const float* s1   = (const float*)d_in[9];
    const float* g2   = (const float*)d_in[10];
    const float* s2   = (const float*)d_in[11];
    float* out = (float*)d_out;

    float *p_ln, *p_q, *p_k, *p_v, *p_ctx, *p_x1, *p_h2;
    float *p_wqkvR, *p_woutR, *p_w1R, *p_w2R;
    cudaGetSymbolAddress((void**)&p_ln,  g_ln);
    cudaGetSymbolAddress((void**)&p_q,   g_q);
    cudaGetSymbolAddress((void**)&p_k,   g_k);
    cudaGetSymbolAddress((void**)&p_v,   g_v);
    cudaGetSymbolAddress((void**)&p_ctx, g_ctx);
    cudaGetSymbolAddress((void**)&p_x1,  g_x1);
    cudaGetSymbolAddress((void**)&p_h2,  g_h2);
    cudaGetSymbolAddress((void**)&p_wqkvR, g_wqkvR);
    cudaGetSymbolAddress((void**)&p_woutR, g_woutR);
    cudaGetSymbolAddress((void**)&p_w1R,   g_w1R);
    cudaGetSymbolAddress((void**)&p_w2R,   g_w2R);

    const int gsmem = (int)sizeof(GSmem);
    const int fsmem = (int)sizeof(FlashSmemT);
    cudaFuncSetAttribute(tfgemm_kernel<1>, cudaFuncAttributeMaxDynamicSharedMemorySize, gsmem);
    cudaFuncSetAttribute(tfgemm_kernel<2>, cudaFuncAttributeMaxDynamicSharedMemorySize, gsmem);
    cudaFuncSetAttribute(tfgemm_kernel<3>, cudaFuncAttributeMaxDynamicSharedMemorySize, gsmem);
    cudaFuncSetAttribute(flash_tc_kernel, cudaFuncAttributeMaxDynamicSharedMemorySize, fsmem);

    // 0) tf32 pre-round of all weights (once per launch; ~15us)
    round_tf32_kernel<<<(DMODEL*3*DMODEL)/1024, 256>>>(Wqkv, p_wqkvR);
    round_tf32_kernel<<<(DMODEL*DMODEL)/1024,   256>>>(Wout, p_woutR);
    round_tf32_kernel<<<(DMODEL*DFF)/1024,      256>>>(W1,   p_w1R);
    round_tf32_kernel<<<(DFF*DMODEL)/1024,      256>>>(W2,   p_w2R);

    // 1) ln1 (rounds its output)
    ln_kernel<<<NTOK, 256>>>(x, g1, s1, p_ln);
    // 2) qkv gemm + scatter to [B,H,S,HD]
    tfgemm_kernel<3><<<dim3(3*DMODEL/128, NTOK/128), 256, gsmem>>>(
        p_ln, p_wqkvR, nullptr, nullptr, nullptr, p_q, p_k, p_v,
        NTOK, 3*DMODEL, DMODEL);
    // 3) causal flash attention (tensor cores; rounds ctx output)
    flash_tc_kernel<<<dim3(SEQ/64, NB*NH), 128, fsmem>>>(p_q, p_k, p_v, p_ctx);
    // 4) out proj + bias + residual(x)
    tfgemm_kernel<1><<<dim3(DMODEL/128, NTOK/128), 256, gsmem>>>(
        p_ctx, p_woutR, bout, x, p_x1, nullptr, nullptr, nullptr,
        NTOK, DMODEL, DMODEL);
    // 5) ln2 (rounds its output)
    ln_kernel<<<NTOK, 256>>>(p_x1, g2, s2, p_ln);
    // 6) W1 + bias + gelu (rounds its output)
    tfgemm_kernel<2><<<dim3(DFF/128, NTOK/128), 256, gsmem>>>(
        p_ln, p_w1R, b1, nullptr, p_h2, nullptr, nullptr, nullptr,
        NTOK, DFF, DMODEL);
    // 7) W2 + bias + residual(x1) -> out
    tfgemm_kernel<1><<<dim3(DMODEL/128, NTOK/128), 256, gsmem>>>(
        p_h2, p_w2R, b2, p_x1, out, nullptr, nullptr, nullptr,
        NTOK, DMODEL, DFF);
}